// round 1
// baseline (speedup 1.0000x reference)
#include <cuda_runtime.h>
#include <cuda_bf16.h>
#include <math.h>

// Problem constants
#define BB 4
#define NN 256
#define TOK (BB*NN)        // 1024
#define OBSD 64
#define QDIM 32
#define HH 256
#define DD 128
#define NOPS 8
#define QE 64

// Output layout (concatenated flatten of the returned tuple)
#define EDGE_OFF 0
#define OP_OFF   (TOK*NN)                 // 262144
#define NEXT_OFF (OP_OFF + TOK*NN*NOPS)   // 2359296

// Scratch (device globals; no allocation allowed)
__device__ float g_lat[TOK * DD];
__device__ float g_EA[TOK * HH];
__device__ float g_EB[TOK * HH];
__device__ float g_OA[TOK * HH];
__device__ float g_OB[TOK * HH];

// ---------------------------------------------------------------------------
// Kernel 1: per-token pipeline, 8 tokens per block, 256 threads.
// ---------------------------------------------------------------------------
// smem layout (floats)
#define S_OBS   0              // 8*64   = 512
#define S_LATIN (S_OBS+512)    // 8*128  = 1024
#define S_Q     (S_LATIN+1024) // 8*32   = 256
#define S_H1    (S_Q+256)      // 8*256  = 2048
#define S_NE    (S_H1+2048)    // 8*256  = 2048
#define S_UPD   (S_NE+2048)    // 8*128  = 1024
#define S_GI    (S_UPD+1024)   // 8*384  = 3072
#define S_GH    (S_GI+3072)    // 8*384  = 3072
#define S_LAT   (S_GH+3072)    // 8*128  = 1024
#define S_QE    (S_LAT+1024)   // 8*64   = 512
#define S_HID   (S_QE+512)     // 8*256  = 2048
#define S_RED   (S_HID+2048)   // 256
#define SM1_FLOATS (S_RED+256) // 16896 floats = 67584 B

__global__ void __launch_bounds__(256)
tok_kernel(const float* __restrict__ obs, const float* __restrict__ latent,
           const float* __restrict__ query,
           const float* __restrict__ enc_w1, const float* __restrict__ enc_b1,
           const float* __restrict__ enc_w2, const float* __restrict__ enc_b2,
           const float* __restrict__ upd_w,  const float* __restrict__ upd_b,
           const float* __restrict__ gru_wi, const float* __restrict__ gru_bi,
           const float* __restrict__ gru_wh, const float* __restrict__ gru_bh,
           const float* __restrict__ eh_w1,  const float* __restrict__ eh_b1,
           const float* __restrict__ oh_w1,  const float* __restrict__ oh_b1,
           const float* __restrict__ q_w,    const float* __restrict__ q_b,
           const float* __restrict__ nh_w1,  const float* __restrict__ nh_b1,
           const float* __restrict__ nh_w2,  const float* __restrict__ nh_b2,
           float* __restrict__ out)
{
    extern __shared__ float sm[];
    const int tid = threadIdx.x;
    const int t0  = blockIdx.x * 8;   // first token of this block

    // ---- load inputs (all contiguous for 8 consecutive tokens) ----
    for (int idx = tid; idx < 8*OBSD; idx += 256) sm[S_OBS+idx]   = obs[(size_t)t0*OBSD + idx];
    for (int idx = tid; idx < 8*DD;   idx += 256) sm[S_LATIN+idx] = latent[(size_t)t0*DD + idx];
    sm[S_Q + tid] = query[(size_t)t0*QDIM + tid];   // 8*32 = 256 exactly
    __syncthreads();

    // ---- h1 = relu(obs @ enc_w1 + b1) ----
    {
        float acc[8];
        float b = enc_b1[tid];
        #pragma unroll
        for (int t = 0; t < 8; t++) acc[t] = b;
        for (int k = 0; k < OBSD; k++) {
            float w = enc_w1[k*HH + tid];
            #pragma unroll
            for (int t = 0; t < 8; t++) acc[t] = fmaf(sm[S_OBS + t*OBSD + k], w, acc[t]);
        }
        #pragma unroll
        for (int t = 0; t < 8; t++) sm[S_H1 + t*HH + tid] = fmaxf(acc[t], 0.0f);
    }
    __syncthreads();

    // ---- node_emb = relu(h1 @ enc_w2 + b2) ----
    {
        float acc[8];
        float b = enc_b2[tid];
        #pragma unroll
        for (int t = 0; t < 8; t++) acc[t] = b;
        for (int k = 0; k < HH; k++) {
            float w = enc_w2[k*HH + tid];
            #pragma unroll
            for (int t = 0; t < 8; t++) acc[t] = fmaf(sm[S_H1 + t*HH + k], w, acc[t]);
        }
        #pragma unroll
        for (int t = 0; t < 8; t++) sm[S_NE + t*HH + tid] = fmaxf(acc[t], 0.0f);
    }
    __syncthreads();

    // ---- upd = node_emb @ upd_w + upd_b (linear) ----
    if (tid < DD) {
        float acc[8];
        float b = upd_b[tid];
        #pragma unroll
        for (int t = 0; t < 8; t++) acc[t] = b;
        for (int k = 0; k < HH; k++) {
            float w = upd_w[k*DD + tid];
            #pragma unroll
            for (int t = 0; t < 8; t++) acc[t] = fmaf(sm[S_NE + t*HH + k], w, acc[t]);
        }
        #pragma unroll
        for (int t = 0; t < 8; t++) sm[S_UPD + t*DD + tid] = acc[t];
    }
    __syncthreads();

    // ---- gi = upd @ gru_wi + bi ; gh = latent @ gru_wh + bh ----
    for (int o = tid; o < 3*DD; o += 256) {
        float ai[8], ah[8];
        float bi_ = gru_bi[o], bh_ = gru_bh[o];
        #pragma unroll
        for (int t = 0; t < 8; t++) { ai[t] = bi_; ah[t] = bh_; }
        for (int k = 0; k < DD; k++) {
            float wi = gru_wi[k*(3*DD) + o];
            float wh = gru_wh[k*(3*DD) + o];
            #pragma unroll
            for (int t = 0; t < 8; t++) {
                ai[t] = fmaf(sm[S_UPD   + t*DD + k], wi, ai[t]);
                ah[t] = fmaf(sm[S_LATIN + t*DD + k], wh, ah[t]);
            }
        }
        #pragma unroll
        for (int t = 0; t < 8; t++) { sm[S_GI + t*(3*DD) + o] = ai[t]; sm[S_GH + t*(3*DD) + o] = ah[t]; }
    }
    __syncthreads();

    // ---- GRU gates ----
    for (int idx = tid; idx < 8*DD; idx += 256) {
        int t = idx >> 7, d = idx & 127;
        float ir = sm[S_GI + t*(3*DD) + d],        hr = sm[S_GH + t*(3*DD) + d];
        float iz = sm[S_GI + t*(3*DD) + DD + d],   hz = sm[S_GH + t*(3*DD) + DD + d];
        float in_ = sm[S_GI + t*(3*DD) + 2*DD + d], hn = sm[S_GH + t*(3*DD) + 2*DD + d];
        float r = 1.0f / (1.0f + expf(-(ir + hr)));
        float z = 1.0f / (1.0f + expf(-(iz + hz)));
        float nh = tanhf(in_ + r * hn);
        float li = sm[S_LATIN + t*DD + d];
        float l  = (1.0f - z) * nh + z * li;
        sm[S_LAT + t*DD + d] = l;
        g_lat[(size_t)(t0 + t)*DD + d] = l;
    }

    // ---- q_emb = relu(query @ q_w + q_b) ----  (independent of gates; but needs s_q only)
    if (tid < QE) {
        float acc[8];
        float b = q_b[tid];
        #pragma unroll
        for (int t = 0; t < 8; t++) acc[t] = b;
        for (int k = 0; k < QDIM; k++) {
            float w = q_w[k*QE + tid];
            #pragma unroll
            for (int t = 0; t < 8; t++) acc[t] = fmaf(sm[S_Q + t*QDIM + k], w, acc[t]);
        }
        #pragma unroll
        for (int t = 0; t < 8; t++) sm[S_QE + t*QE + tid] = fmaxf(acc[t], 0.0f);
    }
    __syncthreads();

    // ---- EA/EB/OA/OB precompute (pair-head rank-1 parts), biases folded into EA/OA ----
    {
        float ea[8], eb[8], oa[8], ob[8];
        float be = eh_b1[tid], bo = oh_b1[tid];
        #pragma unroll
        for (int t = 0; t < 8; t++) { ea[t] = be; eb[t] = 0.f; oa[t] = bo; ob[t] = 0.f; }
        for (int k = 0; k < DD; k++) {
            float wel = eh_w1[k*HH + tid];
            float wer = eh_w1[(DD + k)*HH + tid];
            float wol = oh_w1[k*HH + tid];
            float wor = oh_w1[(DD + k)*HH + tid];
            #pragma unroll
            for (int t = 0; t < 8; t++) {
                float lv = sm[S_LAT + t*DD + k];
                ea[t] = fmaf(lv, wel, ea[t]);
                eb[t] = fmaf(lv, wer, eb[t]);
                oa[t] = fmaf(lv, wol, oa[t]);
                ob[t] = fmaf(lv, wor, ob[t]);
            }
        }
        #pragma unroll
        for (int t = 0; t < 8; t++) {
            size_t p = (size_t)(t0 + t)*HH + tid;
            g_EA[p] = ea[t]; g_EB[p] = eb[t]; g_OA[p] = oa[t]; g_OB[p] = ob[t];
        }
    }

    // ---- hid = relu(concat[lat, node_emb, q_emb] @ nh_w1 + b) ----
    {
        float acc[8];
        float b = nh_b1[tid];
        #pragma unroll
        for (int t = 0; t < 8; t++) acc[t] = b;
        for (int k = 0; k < DD; k++) {
            float w = nh_w1[k*HH + tid];
            #pragma unroll
            for (int t = 0; t < 8; t++) acc[t] = fmaf(sm[S_LAT + t*DD + k], w, acc[t]);
        }
        for (int k = 0; k < HH; k++) {
            float w = nh_w1[(DD + k)*HH + tid];
            #pragma unroll
            for (int t = 0; t < 8; t++) acc[t] = fmaf(sm[S_NE + t*HH + k], w, acc[t]);
        }
        for (int k = 0; k < QE; k++) {
            float w = nh_w1[(DD + HH + k)*HH + tid];
            #pragma unroll
            for (int t = 0; t < 8; t++) acc[t] = fmaf(sm[S_QE + t*QE + k], w, acc[t]);
        }
        #pragma unroll
        for (int t = 0; t < 8; t++) sm[S_HID + t*HH + tid] = fmaxf(acc[t], 0.0f);
    }
    __syncthreads();

    // ---- next_pred = hid @ nh_w2 + b2 (scalar per token); deterministic tree reduce ----
    for (int t = 0; t < 8; t++) {
        sm[S_RED + tid] = sm[S_HID + t*HH + tid] * nh_w2[tid];
        __syncthreads();
        for (int s = 128; s > 0; s >>= 1) {
            if (tid < s) sm[S_RED + tid] += sm[S_RED + tid + s];
            __syncthreads();
        }
        if (tid == 0) out[NEXT_OFF + t0 + t] = sm[S_RED] + nh_b2[0];
        __syncthreads();
    }
}

// ---------------------------------------------------------------------------
// Kernel 2: pair heads. One block per (batch, i, j-half of 128).
// D = |lat_i - lat_j| (128k x 128j) in smem; fp32 GEMM vs W_abs (128x256) for
// edge and op heads; fused relu + second layer; smem tree reductions.
// ---------------------------------------------------------------------------
// smem layout (floats)
#define P_D    0               // 128*128 = 16384 (aliased as part_o in op epilogue)
#define P_WP   16384           // 16*256  = 4096
#define P_PE   20480           // 16*128  = 2048
#define P_EA   22528           // 256
#define P_OA   22784           // 256
#define P_EW2  23040           // 256
#define P_OW2  23296           // 256*8   = 2048
#define P_LATI 25344           // 128
#define SM2_FLOATS (P_LATI+128) // 25472 floats = 101888 B

__global__ void __launch_bounds__(256, 1)
pair_kernel(const float* __restrict__ eh_w1, const float* __restrict__ eh_w2,
            const float* __restrict__ eh_b2,
            const float* __restrict__ oh_w1, const float* __restrict__ oh_w2,
            const float* __restrict__ oh_b2,
            float* __restrict__ out)
{
    extern __shared__ float sm[];
    const int tid = threadIdx.x;
    const int blk = blockIdx.x;
    const int b   = blk >> 9;
    const int i   = (blk >> 1) & 255;
    const int jt  = blk & 1;

    const int ti    = b*NN + i;          // global token index of i
    const int jbase = b*NN + jt*128;     // first global token of this j-half

    const int th = tid >> 4;   // 0..15 : h-group  -> h0 = th*16
    const int tj = tid & 15;   // 0..15 : j-group  -> j = tj + 16*jj
    const int h0 = th * 16;

    // ---- stage per-block constants ----
    if (tid < 128) sm[P_LATI + tid] = g_lat[(size_t)ti*DD + tid];
    sm[P_EA  + tid] = g_EA[(size_t)ti*HH + tid];
    sm[P_OA  + tid] = g_OA[(size_t)ti*HH + tid];
    sm[P_EW2 + tid] = eh_w2[tid];
    for (int idx = tid; idx < HH*NOPS; idx += 256) sm[P_OW2 + idx] = oh_w2[idx];
    __syncthreads();

    // ---- build D[k][j] = |lat_i[k] - lat_j[k]| ----
    {
        int j = tid & 127, half = tid >> 7;
        const float4* latj = reinterpret_cast<const float4*>(&g_lat[(size_t)(jbase + j)*DD]);
        const float4* lati = reinterpret_cast<const float4*>(&sm[P_LATI]);
        for (int q4 = half*16; q4 < half*16 + 16; ++q4) {
            float4 lj = latj[q4];
            float4 li = lati[q4];
            int kb = q4 * 4;
            sm[P_D + (kb+0)*128 + j] = fabsf(li.x - lj.x);
            sm[P_D + (kb+1)*128 + j] = fabsf(li.y - lj.y);
            sm[P_D + (kb+2)*128 + j] = fabsf(li.z - lj.z);
            sm[P_D + (kb+3)*128 + j] = fabsf(li.w - lj.w);
        }
    }
    __syncthreads();

    float acc[8][16];

    // =================== head E: GEMM D @ We_abs ===================
    {
        const float* W = eh_w1 + (size_t)(2*DD)*HH;   // abs block rows
        #pragma unroll
        for (int jj = 0; jj < 8; jj++)
            #pragma unroll
            for (int hh = 0; hh < 16; hh++) acc[jj][hh] = 0.0f;

        for (int p = 0; p < 8; ++p) {
            __syncthreads();
            #pragma unroll
            for (int it = 0; it < 16; ++it)
                sm[P_WP + it*HH + tid] = W[(size_t)(p*16 + it)*HH + tid];
            __syncthreads();
            #pragma unroll 4
            for (int kk = 0; kk < 16; ++kk) {
                int k = p*16 + kk;
                float w[16];
                const float4* wp = reinterpret_cast<const float4*>(&sm[P_WP + kk*HH + h0]);
                reinterpret_cast<float4*>(w)[0] = wp[0];
                reinterpret_cast<float4*>(w)[1] = wp[1];
                reinterpret_cast<float4*>(w)[2] = wp[2];
                reinterpret_cast<float4*>(w)[3] = wp[3];
                float dv[8];
                #pragma unroll
                for (int jj = 0; jj < 8; jj++) dv[jj] = sm[P_D + k*128 + tj + 16*jj];
                #pragma unroll
                for (int jj = 0; jj < 8; jj++)
                    #pragma unroll
                    for (int hh = 0; hh < 16; hh++)
                        acc[jj][hh] = fmaf(dv[jj], w[hh], acc[jj][hh]);
            }
        }
    }

    // ---- epilogue E: relu + dot with eh_w2, tree reduce over 16 h-groups ----
    {
        #pragma unroll
        for (int jj = 0; jj < 8; jj++) {
            int j = tj + 16*jj;
            float eb[16];
            const float4* ebp = reinterpret_cast<const float4*>(&g_EB[(size_t)(jbase + j)*HH + h0]);
            reinterpret_cast<float4*>(eb)[0] = ebp[0];
            reinterpret_cast<float4*>(eb)[1] = ebp[1];
            reinterpret_cast<float4*>(eb)[2] = ebp[2];
            reinterpret_cast<float4*>(eb)[3] = ebp[3];
            float pe = 0.0f;
            #pragma unroll
            for (int hh = 0; hh < 16; hh++) {
                float hv = fmaxf(acc[jj][hh] + sm[P_EA + h0 + hh] + eb[hh], 0.0f);
                pe = fmaf(hv, sm[P_EW2 + h0 + hh], pe);
            }
            sm[P_PE + th*128 + j] = pe;
        }
        __syncthreads();
        if (tid < 128) {
            float e = eh_b2[0];
            #pragma unroll
            for (int u = 0; u < 16; u++) e += sm[P_PE + u*128 + tid];
            int jg = jt*128 + tid;
            if (jg == i) e = -8.0f;
            out[EDGE_OFF + ((size_t)(b*NN + i))*NN + jg] = e;
        }
    }

    // =================== head O: GEMM D @ Wo_abs ===================
    {
        const float* W = oh_w1 + (size_t)(2*DD)*HH;
        #pragma unroll
        for (int jj = 0; jj < 8; jj++)
            #pragma unroll
            for (int hh = 0; hh < 16; hh++) acc[jj][hh] = 0.0f;

        for (int p = 0; p < 8; ++p) {
            __syncthreads();
            #pragma unroll
            for (int it = 0; it < 16; ++it)
                sm[P_WP + it*HH + tid] = W[(size_t)(p*16 + it)*HH + tid];
            __syncthreads();
            #pragma unroll 4
            for (int kk = 0; kk < 16; ++kk) {
                int k = p*16 + kk;
                float w[16];
                const float4* wp = reinterpret_cast<const float4*>(&sm[P_WP + kk*HH + h0]);
                reinterpret_cast<float4*>(w)[0] = wp[0];
                reinterpret_cast<float4*>(w)[1] = wp[1];
                reinterpret_cast<float4*>(w)[2] = wp[2];
                reinterpret_cast<float4*>(w)[3] = wp[3];
                float dv[8];
                #pragma unroll
                for (int jj = 0; jj < 8; jj++) dv[jj] = sm[P_D + k*128 + tj + 16*jj];
                #pragma unroll
                for (int jj = 0; jj < 8; jj++)
                    #pragma unroll
                    for (int hh = 0; hh < 16; hh++)
                        acc[jj][hh] = fmaf(dv[jj], w[hh], acc[jj][hh]);
            }
        }
    }

    // ---- epilogue O: relu + @ oh_w2 [256x8]; part sums in (reused) D smem ----
    __syncthreads();   // last D reads done; safe to alias
    {
        float* partO = &sm[P_D];   // [16 th][128 j][8 kk] = 16384 floats
        #pragma unroll
        for (int jj = 0; jj < 8; jj++) {
            int j = tj + 16*jj;
            float ob[16];
            const float4* obp = reinterpret_cast<const float4*>(&g_OB[(size_t)(jbase + j)*HH + h0]);
            reinterpret_cast<float4*>(ob)[0] = obp[0];
            reinterpret_cast<float4*>(ob)[1] = obp[1];
            reinterpret_cast<float4*>(ob)[2] = obp[2];
            reinterpret_cast<float4*>(ob)[3] = obp[3];
            float po[8];
            #pragma unroll
            for (int kk = 0; kk < 8; kk++) po[kk] = 0.0f;
            #pragma unroll
            for (int hh = 0; hh < 16; hh++) {
                float hv = fmaxf(acc[jj][hh] + sm[P_OA + h0 + hh] + ob[hh], 0.0f);
                #pragma unroll
                for (int kk = 0; kk < 8; kk++)
                    po[kk] = fmaf(hv, sm[P_OW2 + (h0 + hh)*NOPS + kk], po[kk]);
            }
            #pragma unroll
            for (int kk = 0; kk < 8; kk++)
                partO[th*1024 + j*8 + kk] = po[kk];
        }
        __syncthreads();
        for (int idx = tid; idx < 128*NOPS; idx += 256) {
            int j = idx >> 3, kk = idx & 7;
            float o = oh_b2[kk];
            #pragma unroll
            for (int u = 0; u < 16; u++) o += partO[u*1024 + idx];
            int jg = jt*128 + j;
            out[OP_OFF + (((size_t)(b*NN + i))*NN + jg)*NOPS + kk] = o;
        }
    }
}

// ---------------------------------------------------------------------------
extern "C" void kernel_launch(void* const* d_in, const int* in_sizes, int n_in,
                              void* d_out, int out_size)
{
    const float* obs    = (const float*)d_in[0];
    const float* latent = (const float*)d_in[1];
    const float* query  = (const float*)d_in[2];
    const float* enc_w1 = (const float*)d_in[3];
    const float* enc_b1 = (const float*)d_in[4];
    const float* enc_w2 = (const float*)d_in[5];
    const float* enc_b2 = (const float*)d_in[6];
    const float* upd_w  = (const float*)d_in[7];
    const float* upd_b  = (const float*)d_in[8];
    const float* gru_wi = (const float*)d_in[9];
    const float* gru_bi = (const float*)d_in[10];
    const float* gru_wh = (const float*)d_in[11];
    const float* gru_bh = (const float*)d_in[12];
    const float* eh_w1  = (const float*)d_in[13];
    const float* eh_b1  = (const float*)d_in[14];
    const float* eh_w2  = (const float*)d_in[15];
    const float* eh_b2  = (const float*)d_in[16];
    const float* oh_w1  = (const float*)d_in[17];
    const float* oh_b1  = (const float*)d_in[18];
    const float* oh_w2  = (const float*)d_in[19];
    const float* oh_b2  = (const float*)d_in[20];
    const float* q_w    = (const float*)d_in[21];
    const float* q_b    = (const float*)d_in[22];
    const float* nh_w1  = (const float*)d_in[23];
    const float* nh_b1  = (const float*)d_in[24];
    const float* nh_w2  = (const float*)d_in[25];
    const float* nh_b2  = (const float*)d_in[26];
    float* out = (float*)d_out;

    const int sm1 = SM1_FLOATS * sizeof(float);  // 67584
    const int sm2 = SM2_FLOATS * sizeof(float);  // 101888
    cudaFuncSetAttribute(tok_kernel,  cudaFuncAttributeMaxDynamicSharedMemorySize, sm1);
    cudaFuncSetAttribute(pair_kernel, cudaFuncAttributeMaxDynamicSharedMemorySize, sm2);

    tok_kernel<<<TOK/8, 256, sm1>>>(obs, latent, query,
                                    enc_w1, enc_b1, enc_w2, enc_b2,
                                    upd_w, upd_b,
                                    gru_wi, gru_bi, gru_wh, gru_bh,
                                    eh_w1, eh_b1, oh_w1, oh_b1,
                                    q_w, q_b, nh_w1, nh_b1, nh_w2, nh_b2,
                                    out);
    pair_kernel<<<BB*NN*2, 256, sm2>>>(eh_w1, eh_w2, eh_b2,
                                       oh_w1, oh_w2, oh_b2, out);
}

// round 7
// speedup vs baseline: 2.2915x; 2.2915x over previous
#include <cuda_runtime.h>
#include <math.h>
#include <stdint.h>

// Problem constants
#define BB 4
#define NN 256
#define TOK (BB*NN)        // 1024
#define OBSD 64
#define QDIM 32
#define HH 256
#define DD 128
#define NOPS 8
#define QE 64

// Output layout
#define EDGE_OFF 0
#define OP_OFF   (TOK*NN)                 // 262144
#define NEXT_OFF (OP_OFF + TOK*NN*NOPS)   // 2359296

// Scratch
__device__ float g_lat[TOK * DD];
__device__ float g_EA[TOK * HH];
__device__ float g_EB[TOK * HH];
__device__ float g_OA[TOK * HH];
__device__ float g_OB[TOK * HH];

// ---------------------------------------------------------------------------
// helpers
// ---------------------------------------------------------------------------
__device__ __forceinline__ uint32_t f2tf32(float f) {
    uint32_t r;
    asm("cvt.rna.tf32.f32 %0, %1;" : "=r"(r) : "f"(f));
    return r;
}
__device__ __forceinline__ void mma8(float* c, const uint32_t* a, uint32_t b0, uint32_t b1) {
    asm volatile(
        "mma.sync.aligned.m16n8k8.row.col.f32.tf32.tf32.f32 "
        "{%0,%1,%2,%3}, {%4,%5,%6,%7}, {%8,%9}, {%0,%1,%2,%3};"
        : "+f"(c[0]), "+f"(c[1]), "+f"(c[2]), "+f"(c[3])
        : "r"(a[0]), "r"(a[1]), "r"(a[2]), "r"(a[3]), "r"(b0), "r"(b1));
}

// ---------------------------------------------------------------------------
// Kernel 1: per-token pipeline, 8 tokens/block (proven in R1).
// ---------------------------------------------------------------------------
#define S_OBS   0
#define S_LATIN (S_OBS+512)
#define S_Q     (S_LATIN+1024)
#define S_H1    (S_Q+256)
#define S_NE    (S_H1+2048)
#define S_UPD   (S_NE+2048)
#define S_GI    (S_UPD+1024)
#define S_GH    (S_GI+3072)
#define S_LAT   (S_GH+3072)
#define S_QE    (S_LAT+1024)
#define S_HID   (S_QE+512)
#define S_RED   (S_HID+2048)
#define SM1_FLOATS (S_RED+256)

__global__ void __launch_bounds__(256)
tok_kernel(const float* __restrict__ obs, const float* __restrict__ latent,
           const float* __restrict__ query,
           const float* __restrict__ enc_w1, const float* __restrict__ enc_b1,
           const float* __restrict__ enc_w2, const float* __restrict__ enc_b2,
           const float* __restrict__ upd_w,  const float* __restrict__ upd_b,
           const float* __restrict__ gru_wi, const float* __restrict__ gru_bi,
           const float* __restrict__ gru_wh, const float* __restrict__ gru_bh,
           const float* __restrict__ eh_w1,  const float* __restrict__ eh_b1,
           const float* __restrict__ oh_w1,  const float* __restrict__ oh_b1,
           const float* __restrict__ q_w,    const float* __restrict__ q_b,
           const float* __restrict__ nh_w1,  const float* __restrict__ nh_b1,
           const float* __restrict__ nh_w2,  const float* __restrict__ nh_b2,
           float* __restrict__ out)
{
    extern __shared__ float sm[];
    const int tid = threadIdx.x;
    const int t0  = blockIdx.x * 8;

    for (int idx = tid; idx < 8*OBSD; idx += 256) sm[S_OBS+idx]   = obs[(size_t)t0*OBSD + idx];
    for (int idx = tid; idx < 8*DD;   idx += 256) sm[S_LATIN+idx] = latent[(size_t)t0*DD + idx];
    sm[S_Q + tid] = query[(size_t)t0*QDIM + tid];
    __syncthreads();

    {
        float acc[8];
        float b = enc_b1[tid];
        #pragma unroll
        for (int t = 0; t < 8; t++) acc[t] = b;
        for (int k = 0; k < OBSD; k++) {
            float w = enc_w1[k*HH + tid];
            #pragma unroll
            for (int t = 0; t < 8; t++) acc[t] = fmaf(sm[S_OBS + t*OBSD + k], w, acc[t]);
        }
        #pragma unroll
        for (int t = 0; t < 8; t++) sm[S_H1 + t*HH + tid] = fmaxf(acc[t], 0.0f);
    }
    __syncthreads();

    {
        float acc[8];
        float b = enc_b2[tid];
        #pragma unroll
        for (int t = 0; t < 8; t++) acc[t] = b;
        for (int k = 0; k < HH; k++) {
            float w = enc_w2[k*HH + tid];
            #pragma unroll
            for (int t = 0; t < 8; t++) acc[t] = fmaf(sm[S_H1 + t*HH + k], w, acc[t]);
        }
        #pragma unroll
        for (int t = 0; t < 8; t++) sm[S_NE + t*HH + tid] = fmaxf(acc[t], 0.0f);
    }
    __syncthreads();

    if (tid < DD) {
        float acc[8];
        float b = upd_b[tid];
        #pragma unroll
        for (int t = 0; t < 8; t++) acc[t] = b;
        for (int k = 0; k < HH; k++) {
            float w = upd_w[k*DD + tid];
            #pragma unroll
            for (int t = 0; t < 8; t++) acc[t] = fmaf(sm[S_NE + t*HH + k], w, acc[t]);
        }
        #pragma unroll
        for (int t = 0; t < 8; t++) sm[S_UPD + t*DD + tid] = acc[t];
    }
    __syncthreads();

    for (int o = tid; o < 3*DD; o += 256) {
        float ai[8], ah[8];
        float bi_ = gru_bi[o], bh_ = gru_bh[o];
        #pragma unroll
        for (int t = 0; t < 8; t++) { ai[t] = bi_; ah[t] = bh_; }
        for (int k = 0; k < DD; k++) {
            float wi = gru_wi[k*(3*DD) + o];
            float wh = gru_wh[k*(3*DD) + o];
            #pragma unroll
            for (int t = 0; t < 8; t++) {
                ai[t] = fmaf(sm[S_UPD   + t*DD + k], wi, ai[t]);
                ah[t] = fmaf(sm[S_LATIN + t*DD + k], wh, ah[t]);
            }
        }
        #pragma unroll
        for (int t = 0; t < 8; t++) { sm[S_GI + t*(3*DD) + o] = ai[t]; sm[S_GH + t*(3*DD) + o] = ah[t]; }
    }
    __syncthreads();

    for (int idx = tid; idx < 8*DD; idx += 256) {
        int t = idx >> 7, d = idx & 127;
        float ir = sm[S_GI + t*(3*DD) + d],        hr = sm[S_GH + t*(3*DD) + d];
        float iz = sm[S_GI + t*(3*DD) + DD + d],   hz = sm[S_GH + t*(3*DD) + DD + d];
        float in_ = sm[S_GI + t*(3*DD) + 2*DD + d], hn = sm[S_GH + t*(3*DD) + 2*DD + d];
        float r = 1.0f / (1.0f + expf(-(ir + hr)));
        float z = 1.0f / (1.0f + expf(-(iz + hz)));
        float nh = tanhf(in_ + r * hn);
        float li = sm[S_LATIN + t*DD + d];
        float l  = (1.0f - z) * nh + z * li;
        sm[S_LAT + t*DD + d] = l;
        g_lat[(size_t)(t0 + t)*DD + d] = l;
    }

    if (tid < QE) {
        float acc[8];
        float b = q_b[tid];
        #pragma unroll
        for (int t = 0; t < 8; t++) acc[t] = b;
        for (int k = 0; k < QDIM; k++) {
            float w = q_w[k*QE + tid];
            #pragma unroll
            for (int t = 0; t < 8; t++) acc[t] = fmaf(sm[S_Q + t*QDIM + k], w, acc[t]);
        }
        #pragma unroll
        for (int t = 0; t < 8; t++) sm[S_QE + t*QE + tid] = fmaxf(acc[t], 0.0f);
    }
    __syncthreads();

    {
        float ea[8], eb[8], oa[8], ob[8];
        float be = eh_b1[tid], bo = oh_b1[tid];
        #pragma unroll
        for (int t = 0; t < 8; t++) { ea[t] = be; eb[t] = 0.f; oa[t] = bo; ob[t] = 0.f; }
        for (int k = 0; k < DD; k++) {
            float wel = eh_w1[k*HH + tid];
            float wer = eh_w1[(DD + k)*HH + tid];
            float wol = oh_w1[k*HH + tid];
            float wor = oh_w1[(DD + k)*HH + tid];
            #pragma unroll
            for (int t = 0; t < 8; t++) {
                float lv = sm[S_LAT + t*DD + k];
                ea[t] = fmaf(lv, wel, ea[t]);
                eb[t] = fmaf(lv, wer, eb[t]);
                oa[t] = fmaf(lv, wol, oa[t]);
                ob[t] = fmaf(lv, wor, ob[t]);
            }
        }
        #pragma unroll
        for (int t = 0; t < 8; t++) {
            size_t p = (size_t)(t0 + t)*HH + tid;
            g_EA[p] = ea[t]; g_EB[p] = eb[t]; g_OA[p] = oa[t]; g_OB[p] = ob[t];
        }
    }

    {
        float acc[8];
        float b = nh_b1[tid];
        #pragma unroll
        for (int t = 0; t < 8; t++) acc[t] = b;
        for (int k = 0; k < DD; k++) {
            float w = nh_w1[k*HH + tid];
            #pragma unroll
            for (int t = 0; t < 8; t++) acc[t] = fmaf(sm[S_LAT + t*DD + k], w, acc[t]);
        }
        for (int k = 0; k < HH; k++) {
            float w = nh_w1[(DD + k)*HH + tid];
            #pragma unroll
            for (int t = 0; t < 8; t++) acc[t] = fmaf(sm[S_NE + t*HH + k], w, acc[t]);
        }
        for (int k = 0; k < QE; k++) {
            float w = nh_w1[(DD + HH + k)*HH + tid];
            #pragma unroll
            for (int t = 0; t < 8; t++) acc[t] = fmaf(sm[S_QE + t*QE + k], w, acc[t]);
        }
        #pragma unroll
        for (int t = 0; t < 8; t++) sm[S_HID + t*HH + tid] = fmaxf(acc[t], 0.0f);
    }
    __syncthreads();

    for (int t = 0; t < 8; t++) {
        sm[S_RED + tid] = sm[S_HID + t*HH + tid] * nh_w2[tid];
        __syncthreads();
        for (int s = 128; s > 0; s >>= 1) {
            if (tid < s) sm[S_RED + tid] += sm[S_RED + tid + s];
            __syncthreads();
        }
        if (tid == 0) out[NEXT_OFF + t0 + t] = sm[S_RED] + nh_b2[0];
        __syncthreads();
    }
}

// ---------------------------------------------------------------------------
// Kernel 2: persistent tf32 mma.sync pair kernel.
// 148 CTAs x 256 thr. CTAs [0,56) = edge head, [56,148) = op head.
// Tile g in [0,2048): b=g>>9, i=(g>>1)&255, jt=g&1.
// Per tile: D[128j x 128k] tf32 in smem; 8 warps (2j x 4h) each compute a
// 64x64 block of hidden = D @ W_abs via mma.m16n8k8; fused epilogue.
// ---------------------------------------------------------------------------
#define DSTRIDE 132   // floats per D row (pad: conflict-free A frags)
#define WSTRIDE 264   // floats per W row (pad: conflict-free B frags)
#define SB_D    0                     // 128*132*4 = 67584 B (reused as partO)
#define SB_W    67584                 // 128*264*4 = 135168 B
#define SB_W2   (SB_W + 135168)       // 202752: 2048 f
#define SB_EA   (SB_W2 + 8192)        // 210944: 256 f
#define SB_REDB (SB_EA + 1024)        // 211968: 2048 f
#define SB_LATI (SB_REDB + 8192)      // 220160: 128 f
#define SB_TOTAL (SB_LATI + 512)      // 220672 B

#define N_EDGE_CTAS 56
#define N_CTAS 148

__global__ void __launch_bounds__(256, 1)
pair_kernel(const float* __restrict__ eh_w1, const float* __restrict__ eh_w2,
            const float* __restrict__ eh_b2,
            const float* __restrict__ oh_w1, const float* __restrict__ oh_w2,
            const float* __restrict__ oh_b2,
            float* __restrict__ out)
{
    extern __shared__ char smraw[];
    uint32_t* dD    = (uint32_t*)(smraw + SB_D);
    uint32_t* dW    = (uint32_t*)(smraw + SB_W);
    float*    smW2  = (float*)(smraw + SB_W2);
    float*    smEA  = (float*)(smraw + SB_EA);
    float*    smRED = (float*)(smraw + SB_REDB);
    float*    smLAT = (float*)(smraw + SB_LATI);
    float*    partO = (float*)(smraw + SB_D);   // aliases D (dead after mma+sync)

    const int tid  = threadIdx.x;
    const int wid  = tid >> 5;
    const int lane = tid & 31;
    const int gid  = lane >> 2;     // 0..7
    const int tg   = lane & 3;      // 0..3
    const int wj   = wid & 1;       // j half
    const int wh   = wid >> 1;      // h quarter
    const int j0   = wj * 64;
    const int h0   = wh * 64;

    int head, pos, npos;
    if (blockIdx.x < N_EDGE_CTAS) { head = 0; pos = blockIdx.x;               npos = N_EDGE_CTAS; }
    else                          { head = 1; pos = blockIdx.x - N_EDGE_CTAS; npos = N_CTAS - N_EDGE_CTAS; }

    // ---- stage W_abs (tf32) once per CTA ----
    {
        const float* Wsrc = (head ? oh_w1 : eh_w1) + (size_t)(2*DD)*HH;
        for (int idx = tid; idx < DD*HH; idx += 256) {
            int k = idx >> 8, h = idx & 255;
            dW[k*WSTRIDE + h] = f2tf32(Wsrc[idx]);
        }
        if (head == 0) { if (tid < 256) smW2[tid] = eh_w2[tid]; }
        else           { for (int idx = tid; idx < HH*NOPS; idx += 256) smW2[idx] = oh_w2[idx]; }
    }

    const float* XA = head ? g_OA : g_EA;
    const float* XB = head ? g_OB : g_EB;

    for (int g = pos; g < 2048; g += npos) {
        const int b = g >> 9, i = (g >> 1) & 255, jt = g & 1;
        const int ti = b*NN + i;
        const int jbase = b*NN + jt*128;

        __syncthreads();   // previous epilogue done before overwriting smEA/D
        if (tid < 128) smLAT[tid] = g_lat[(size_t)ti*DD + tid];
        smEA[tid] = XA[(size_t)ti*HH + tid];
        __syncthreads();

        // ---- build D[j][k] = tf32(|lat_i - lat_j|), row-major stride 132 ----
        {
            const float4 li = ((const float4*)smLAT)[lane];
            #pragma unroll
            for (int jj = 0; jj < 16; ++jj) {
                int j = wid*16 + jj;
                float4 lj = ((const float4*)(g_lat + (size_t)(jbase + j)*DD))[lane];
                uint32_t* dst = dD + j*DSTRIDE + lane*4;
                dst[0] = f2tf32(fabsf(li.x - lj.x));
                dst[1] = f2tf32(fabsf(li.y - lj.y));
                dst[2] = f2tf32(fabsf(li.z - lj.z));
                dst[3] = f2tf32(fabsf(li.w - lj.w));
            }
        }
        __syncthreads();

        // ---- mma phase: hidden[64j x 64h] per warp ----
        float c[4][8][4];
        #pragma unroll
        for (int mt = 0; mt < 4; ++mt)
            #pragma unroll
            for (int nt = 0; nt < 8; ++nt)
                #pragma unroll
                for (int q = 0; q < 4; ++q) c[mt][nt][q] = 0.0f;

        const uint32_t* Abase = dD + (j0 + gid)*DSTRIDE + tg;
        const uint32_t* Bbase = dW + tg*WSTRIDE + h0 + gid;

        for (int ks = 0; ks < 16; ++ks) {
            uint32_t a[4][4];
            #pragma unroll
            for (int mt = 0; mt < 4; ++mt) {
                const uint32_t* ap = Abase + mt*16*DSTRIDE + ks*8;
                a[mt][0] = ap[0];
                a[mt][1] = ap[8*DSTRIDE];
                a[mt][2] = ap[4];
                a[mt][3] = ap[8*DSTRIDE + 4];
            }
            const uint32_t* bp0 = Bbase + ks*8*WSTRIDE;
            #pragma unroll
            for (int nt = 0; nt < 8; ++nt) {
                uint32_t b0 = bp0[nt*8];
                uint32_t b1 = bp0[4*WSTRIDE + nt*8];
                #pragma unroll
                for (int mt = 0; mt < 4; ++mt)
                    mma8(c[mt][nt], a[mt], b0, b1);
            }
        }
        __syncthreads();   // all warps done reading D before partO aliases it

        // ---- epilogue ----
        if (head == 0) {
            #pragma unroll
            for (int mt = 0; mt < 4; ++mt) {
                #pragma unroll
                for (int rh = 0; rh < 2; ++rh) {
                    int jl = j0 + mt*16 + gid + rh*8;
                    const float* ebrow = XB + (size_t)(jbase + jl)*HH;
                    float part = 0.0f;
                    #pragma unroll
                    for (int nt = 0; nt < 8; ++nt) {
                        int ha = h0 + nt*8 + 2*tg;
                        float2 eb = *(const float2*)(ebrow + ha);
                        float hv0 = fmaxf(c[mt][nt][rh*2+0] + smEA[ha]   + eb.x, 0.0f);
                        float hv1 = fmaxf(c[mt][nt][rh*2+1] + smEA[ha+1] + eb.y, 0.0f);
                        part = fmaf(hv0, smW2[ha],   part);
                        part = fmaf(hv1, smW2[ha+1], part);
                    }
                    smRED[(wh*4 + tg)*128 + jl] = part;
                }
            }
            __syncthreads();
            if (tid < 128) {
                float v = eh_b2[0];
                #pragma unroll
                for (int u = 0; u < 16; ++u) v += smRED[u*128 + tid];
                int jg = jt*128 + tid;
                if (jg == i) v = -8.0f;
                out[EDGE_OFF + (size_t)ti*NN + jg] = v;
            }
        } else {
            #pragma unroll
            for (int mt = 0; mt < 4; ++mt) {
                #pragma unroll
                for (int rh = 0; rh < 2; ++rh) {
                    int jl = j0 + mt*16 + gid + rh*8;
                    const float* obrow = XB + (size_t)(jbase + jl)*HH;
                    float po[8];
                    #pragma unroll
                    for (int k = 0; k < 8; ++k) po[k] = 0.0f;
                    #pragma unroll
                    for (int nt = 0; nt < 8; ++nt) {
                        int ha = h0 + nt*8 + 2*tg;
                        float2 ob = *(const float2*)(obrow + ha);
                        float hv0 = fmaxf(c[mt][nt][rh*2+0] + smEA[ha]   + ob.x, 0.0f);
                        float hv1 = fmaxf(c[mt][nt][rh*2+1] + smEA[ha+1] + ob.y, 0.0f);
                        const float* w0 = smW2 + ha*8;
                        const float* w1 = smW2 + (ha+1)*8;
                        #pragma unroll
                        for (int k = 0; k < 8; ++k) {
                            po[k] = fmaf(hv0, w0[k], po[k]);
                            po[k] = fmaf(hv1, w1[k], po[k]);
                        }
                    }
                    float* pdst = partO + (wh*4 + tg)*1024 + jl*8;
                    *(float4*)(pdst)     = make_float4(po[0], po[1], po[2], po[3]);
                    *(float4*)(pdst + 4) = make_float4(po[4], po[5], po[6], po[7]);
                }
            }
            __syncthreads();
            for (int idx = tid; idx < 1024; idx += 256) {
                float v = oh_b2[idx & 7];
                #pragma unroll
                for (int u = 0; u < 16; ++u) v += partO[u*1024 + idx];
                out[OP_OFF + ((size_t)ti*NN + jt*128 + (idx >> 3))*NOPS + (idx & 7)] = v;
            }
        }
    }
}

// ---------------------------------------------------------------------------
extern "C" void kernel_launch(void* const* d_in, const int* in_sizes, int n_in,
                              void* d_out, int out_size)
{
    const float* obs    = (const float*)d_in[0];
    const float* latent = (const float*)d_in[1];
    const float* query  = (const float*)d_in[2];
    const float* enc_w1 = (const float*)d_in[3];
    const float* enc_b1 = (const float*)d_in[4];
    const float* enc_w2 = (const float*)d_in[5];
    const float* enc_b2 = (const float*)d_in[6];
    const float* upd_w  = (const float*)d_in[7];
    const float* upd_b  = (const float*)d_in[8];
    const float* gru_wi = (const float*)d_in[9];
    const float* gru_bi = (const float*)d_in[10];
    const float* gru_wh = (const float*)d_in[11];
    const float* gru_bh = (const float*)d_in[12];
    const float* eh_w1  = (const float*)d_in[13];
    const float* eh_b1  = (const float*)d_in[14];
    const float* eh_w2  = (const float*)d_in[15];
    const float* eh_b2  = (const float*)d_in[16];
    const float* oh_w1  = (const float*)d_in[17];
    const float* oh_b1  = (const float*)d_in[18];
    const float* oh_w2  = (const float*)d_in[19];
    const float* oh_b2  = (const float*)d_in[20];
    const float* q_w    = (const float*)d_in[21];
    const float* q_b    = (const float*)d_in[22];
    const float* nh_w1  = (const float*)d_in[23];
    const float* nh_b1  = (const float*)d_in[24];
    const float* nh_w2  = (const float*)d_in[25];
    const float* nh_b2  = (const float*)d_in[26];
    float* out = (float*)d_out;

    const int sm1 = SM1_FLOATS * sizeof(float);
    cudaFuncSetAttribute(tok_kernel,  cudaFuncAttributeMaxDynamicSharedMemorySize, sm1);
    cudaFuncSetAttribute(pair_kernel, cudaFuncAttributeMaxDynamicSharedMemorySize, SB_TOTAL);

    tok_kernel<<<TOK/8, 256, sm1>>>(obs, latent, query,
                                    enc_w1, enc_b1, enc_w2, enc_b2,
                                    upd_w, upd_b,
                                    gru_wi, gru_bi, gru_wh, gru_bh,
                                    eh_w1, eh_b1, oh_w1, oh_b1,
                                    q_w, q_b, nh_w1, nh_b1, nh_w2, nh_b2,
                                    out);
    pair_kernel<<<N_CTAS, 256, SB_TOTAL>>>(eh_w1, eh_w2, eh_b2,
                                           oh_w1, oh_w2, oh_b2, out);
}